// round 3
// baseline (speedup 1.0000x reference)
#include <cuda_runtime.h>
#include <cstdint>

// Problem constants
#define D_   128
#define K_   1024
#define N_   65536            // B*T = 16*4096
#define DECAY 0.99f
#define EPSV  1e-5f
#define VQ_COMMIT 0.25f
#define REPAIR_THRESH 0.02f

// Output layout (floats), concatenated in reference return order
#define O_Q     0
#define O_DIFF  8388608
#define O_CODE  8388609
#define O_EMB   8454145
#define O_CS    8585217
#define O_MEAN  8586241

// -------- device scratch (no allocations allowed) --------
__device__ float g_embT[K_ * D_];     // embedding transposed [K][D]
__device__ float g_enorm[K_];         // ||e_k||^2
__device__ int   g_code[N_];          // argmin indices
__device__ float g_counts[K_];        // per-code counts
__device__ float g_embSumT[K_ * D_];  // per-code x-sum, [K][D] layout
__device__ float g_diff;              // sum of (q-x)^2
__device__ float g_n;                 // sum(new_cluster_size)
__device__ int   g_nrepair;           // # rows needing exact recompute
__device__ int   g_repair[N_];        // worklist of row ids

// -------- f32x2 packed FMA (Blackwell) --------
__device__ __forceinline__ unsigned long long ffma2(unsigned long long a,
                                                    unsigned long long b,
                                                    unsigned long long c) {
    unsigned long long d;
    asm("fma.rn.f32x2 %0, %1, %2, %3;" : "=l"(d) : "l"(a), "l"(b), "l"(c));
    return d;
}
__device__ __forceinline__ float lo32(unsigned long long v) {
    return __uint_as_float((unsigned)(v & 0xffffffffull));
}
__device__ __forceinline__ float hi32(unsigned long long v) {
    return __uint_as_float((unsigned)(v >> 32));
}

// ============================================================
// 0) zero scratch
// ============================================================
__global__ void zero_kernel() {
    int idx = blockIdx.x * blockDim.x + threadIdx.x;
    if (idx < K_ * D_) g_embSumT[idx] = 0.0f;
    else if (idx < K_ * D_ + K_) g_counts[idx - K_ * D_] = 0.0f;
    else if (idx == K_ * D_ + K_) { g_diff = 0.0f; g_nrepair = 0; }
}

// ============================================================
// 1) enorm: ||e_k||^2 (coalesced over k)
// ============================================================
__global__ void enorm_kernel(const float* __restrict__ E) {
    int k = blockIdx.x * blockDim.x + threadIdx.x;
    if (k >= K_) return;
    float s = 0.0f;
#pragma unroll 8
    for (int d = 0; d < D_; d++) {
        float v = E[d * K_ + k];
        s = fmaf(v, v, s);
    }
    g_enorm[k] = s;
}

// ============================================================
// 2) transpose embedding [D,K] -> [K,D]
// ============================================================
__global__ void transpose_kernel(const float* __restrict__ E) {
    __shared__ float tile[32][33];
    int k = blockIdx.x * 32 + threadIdx.x;
    int d = blockIdx.y * 32 + threadIdx.y;
    tile[threadIdx.y][threadIdx.x] = E[d * K_ + k];
    __syncthreads();
    int k2 = blockIdx.x * 32 + threadIdx.y;
    int d2 = blockIdx.y * 32 + threadIdx.x;
    g_embT[k2 * D_ + d2] = tile[threadIdx.x][threadIdx.y];
}

// ============================================================
// 3) argmin kernel: per 64-row block, scan all 1024 codes.
//    dist' = ||e||^2 - 2 x.e  (||x||^2 constant per row)
//    Tracks best AND second-best; near-ties go to fp64 repair.
// ============================================================
#define BM 64
#define BN 128
#define ESTRIDE 130
#define SMEM_FLOATS (BM * D_ + BN * ESTRIDE + BN)

__global__ __launch_bounds__(256, 2)
void argmin_kernel(const float* __restrict__ in, const float* __restrict__ E,
                   float* __restrict__ out_code) {
    extern __shared__ float sm[];
    float* Xs  = sm;                          // [BM][128]
    float* Es  = sm + BM * D_;                // [BN][ESTRIDE]
    float* ens = sm + BM * D_ + BN * ESTRIDE; // [BN]

    const int tid  = threadIdx.x;
    const int warp = tid >> 5;
    const int lane = tid & 31;
    const int row0 = blockIdx.x * BM;
    const int r0   = warp * 8;                // this warp's 8 rows

    // load X tile (float4, coalesced)
    {
        const float4* gin = (const float4*)(in + row0 * D_);
        float4* xs4 = (float4*)Xs;
#pragma unroll
        for (int i = 0; i < 8; i++) xs4[tid + i * 256] = gin[tid + i * 256];
    }

    float best[8], best2[8];
    int   bidx[8];
#pragma unroll
    for (int r = 0; r < 8; r++) { best[r] = 3.4e38f; best2[r] = 3.4e38f; bidx[r] = 0; }

    for (int t = 0; t < K_ / BN; t++) {
        const int c0 = t * BN;
        __syncthreads();
        // load E tile transposed into smem [c][d], float4 over c
        {
            const float4* Eg = (const float4*)(E);
#pragma unroll
            for (int ii = 0; ii < 16; ii++) {
                int i = tid + ii * 256;          // i in [0,4096)
                int d = i >> 5;                  // 128 d
                int cq = (i & 31) * 4;           // 128 c in groups of 4
                float4 v = Eg[(d * K_ + c0 + cq) >> 2];
                Es[(cq + 0) * ESTRIDE + d] = v.x;
                Es[(cq + 1) * ESTRIDE + d] = v.y;
                Es[(cq + 2) * ESTRIDE + d] = v.z;
                Es[(cq + 3) * ESTRIDE + d] = v.w;
            }
            if (tid < BN) ens[tid] = g_enorm[c0 + tid];
        }
        __syncthreads();

        unsigned long long acc[8][4];
#pragma unroll
        for (int r = 0; r < 8; r++)
#pragma unroll
            for (int j = 0; j < 4; j++) acc[r][j] = 0ull;

        // codes for this thread: lane + 32*j
#pragma unroll 4
        for (int d2 = 0; d2 < D_ / 2; d2++) {
            unsigned long long ev[4];
#pragma unroll
            for (int j = 0; j < 4; j++)
                ev[j] = *(const unsigned long long*)&Es[(lane + 32 * j) * ESTRIDE + 2 * d2];
#pragma unroll
            for (int r = 0; r < 8; r++) {
                unsigned long long xv =
                    *(const unsigned long long*)&Xs[(r0 + r) * D_ + 2 * d2];
#pragma unroll
                for (int j = 0; j < 4; j++)
                    acc[r][j] = ffma2(xv, ev[j], acc[r][j]);
            }
        }

        // fold into running (best, second-best)
#pragma unroll
        for (int j = 0; j < 4; j++) {
            int c = lane + 32 * j;
            float en = ens[c];
            int gidx = c0 + c;
#pragma unroll
            for (int r = 0; r < 8; r++) {
                float dot = lo32(acc[r][j]) + hi32(acc[r][j]);
                float dist = en - 2.0f * dot;
                if (dist < best[r] || (dist == best[r] && gidx < bidx[r])) {
                    best2[r] = best[r];
                    best[r] = dist; bidx[r] = gidx;
                } else {
                    best2[r] = fminf(best2[r], dist);
                }
            }
        }
    }

    // warp reduction per row, carrying second-best
#pragma unroll
    for (int r = 0; r < 8; r++) {
        float b1 = best[r], b2 = best2[r]; int i1 = bidx[r];
#pragma unroll
        for (int off = 16; off > 0; off >>= 1) {
            float ob1 = __shfl_down_sync(0xffffffffu, b1, off);
            int   oi1 = __shfl_down_sync(0xffffffffu, i1, off);
            float ob2 = __shfl_down_sync(0xffffffffu, b2, off);
            if (ob1 < b1 || (ob1 == b1 && oi1 < i1)) {
                b2 = fminf(b1, ob2);
                b1 = ob1; i1 = oi1;
            } else {
                b2 = fminf(b2, ob1);
            }
        }
        if (lane == 0) {
            int row = row0 + r0 + r;
            g_code[row] = i1;
            out_code[row] = (float)i1;
            if (b2 - b1 < REPAIR_THRESH) {
                int slot = atomicAdd(&g_nrepair, 1);
                if (slot < N_) g_repair[slot] = row;
            }
        }
    }
}

// ============================================================
// 3b) repair: fp64 exact argmin for near-tie rows
// ============================================================
__global__ void repair_kernel(const float* __restrict__ in,
                              const float* __restrict__ E,
                              float* __restrict__ out_code) {
    __shared__ float xs[D_];
    __shared__ double sb[256];
    __shared__ int si[256];
    int nrep = g_nrepair;
    if (nrep > N_) nrep = N_;
    for (int it = blockIdx.x; it < nrep; it += gridDim.x) {
        int row = g_repair[it];
        if (threadIdx.x < D_) xs[threadIdx.x] = in[row * D_ + threadIdx.x];
        __syncthreads();
        double b = 1e300; int bi = 0;
        for (int k = threadIdx.x; k < K_; k += 256) {
            double s = 0.0;
#pragma unroll 8
            for (int d = 0; d < D_; d++) {
                double df = (double)xs[d] - (double)E[d * K_ + k];
                s = fma(df, df, s);
            }
            if (s < b) { b = s; bi = k; }
        }
        sb[threadIdx.x] = b; si[threadIdx.x] = bi;
        __syncthreads();
        for (int off = 128; off > 0; off >>= 1) {
            if (threadIdx.x < off) {
                double ob = sb[threadIdx.x + off];
                int oi = si[threadIdx.x + off];
                if (ob < sb[threadIdx.x] ||
                    (ob == sb[threadIdx.x] && oi < si[threadIdx.x])) {
                    sb[threadIdx.x] = ob; si[threadIdx.x] = oi;
                }
            }
            __syncthreads();
        }
        if (threadIdx.x == 0) {
            g_code[row] = si[0];
            out_code[row] = (float)si[0];
        }
        __syncthreads();
    }
}

// ============================================================
// 4) gather + stats: quantize output, diff, counts, embSum
//    one warp per row
// ============================================================
__global__ void gather_stats_kernel(const float* __restrict__ in,
                                    float* __restrict__ out_q) {
    const int warp = threadIdx.x >> 5;
    const int lane = threadIdx.x & 31;
    const int row = blockIdx.x * 8 + warp;
    const int k = g_code[row];

    float4 x4 = ((const float4*)in)[row * 32 + lane];
    float4 q4 = ((const float4*)g_embT)[k * 32 + lane];
    ((float4*)out_q)[row * 32 + lane] = q4;

    float dx = q4.x - x4.x, dy = q4.y - x4.y, dz = q4.z - x4.z, dw = q4.w - x4.w;
    float s = dx * dx + dy * dy + dz * dz + dw * dw;
#pragma unroll
    for (int off = 16; off > 0; off >>= 1)
        s += __shfl_down_sync(0xffffffffu, s, off);
    if (lane == 0) {
        atomicAdd(&g_diff, s);
        atomicAdd(&g_counts[k], 1.0f);
    }
    int base = k * D_ + lane * 4;
    atomicAdd(&g_embSumT[base + 0], x4.x);
    atomicAdd(&g_embSumT[base + 1], x4.y);
    atomicAdd(&g_embSumT[base + 2], x4.z);
    atomicAdd(&g_embSumT[base + 3], x4.w);
}

// ============================================================
// 5) finalize A: new_cluster_size, n, diff scalar
// ============================================================
__global__ void finalizeA_kernel(const float* __restrict__ cs_in,
                                 float* __restrict__ out) {
    __shared__ float wsum[32];
    int k = threadIdx.x;
    float ncs = cs_in[k] * DECAY + (1.0f - DECAY) * g_counts[k];
    out[O_CS + k] = ncs;

    float s = ncs;
#pragma unroll
    for (int off = 16; off > 0; off >>= 1)
        s += __shfl_down_sync(0xffffffffu, s, off);
    if ((k & 31) == 0) wsum[k >> 5] = s;
    __syncthreads();
    if (k < 32) {
        float v = wsum[k];
#pragma unroll
        for (int off = 16; off > 0; off >>= 1)
            v += __shfl_down_sync(0xffffffffu, v, off);
        if (k == 0) {
            g_n = v;
            out[O_DIFF] = VQ_COMMIT * g_diff / (float)(N_ * D_);
        }
    }
}

// ============================================================
// 6) finalize B: new_embedding_mean, new_embedding
// ============================================================
__global__ void finalizeB_kernel(const float* __restrict__ mean_in,
                                 float* __restrict__ out) {
    int idx = blockIdx.x * blockDim.x + threadIdx.x;  // [D,K] row-major
    if (idx >= D_ * K_) return;
    int d = idx >> 10;          // / K_
    int k = idx & (K_ - 1);
    float em = mean_in[idx] * DECAY + (1.0f - DECAY) * g_embSumT[k * D_ + d];
    out[O_MEAN + idx] = em;
    float n = g_n;
    float ncs = out[O_CS + k];
    float cs = (ncs + EPSV) / (n + K_ * EPSV) * n;
    out[O_EMB + idx] = em / cs;
}

// ============================================================
extern "C" void kernel_launch(void* const* d_in, const int* in_sizes, int n_in,
                              void* d_out, int out_size) {
    const float* in      = (const float*)d_in[0];  // [B,T,D]
    const float* emb     = (const float*)d_in[1];  // [D,K]
    const float* cs_in   = (const float*)d_in[2];  // [K]
    const float* mean_in = (const float*)d_in[3];  // [D,K]
    float* out = (float*)d_out;

    static bool attr_set = false;
    if (!attr_set) {
        cudaFuncSetAttribute(argmin_kernel,
                             cudaFuncAttributeMaxDynamicSharedMemorySize,
                             SMEM_FLOATS * sizeof(float));
        attr_set = true;
    }

    zero_kernel<<<(K_ * D_ + K_ + 1 + 255) / 256, 256>>>();
    enorm_kernel<<<K_ / 256, 256>>>(emb);
    transpose_kernel<<<dim3(K_ / 32, D_ / 32), dim3(32, 32)>>>(emb);
    argmin_kernel<<<N_ / BM, 256, SMEM_FLOATS * sizeof(float)>>>(
        in, emb, out + O_CODE);
    repair_kernel<<<128, 256>>>(in, emb, out + O_CODE);
    gather_stats_kernel<<<N_ / 8, 256>>>(in, out + O_Q);
    finalizeA_kernel<<<1, 1024>>>(cs_in, out);
    finalizeB_kernel<<<(D_ * K_ + 255) / 256, 256>>>(mean_in, out);
}

// round 6
// speedup vs baseline: 2.4820x; 2.4820x over previous
#include <cuda_runtime.h>
#include <cstdint>

// Problem constants
#define D_   128
#define K_   1024
#define N_   65536            // B*T = 16*4096
#define DECAY 0.99f
#define EPSV  1e-5f
#define VQ_COMMIT 0.25f
#define REPAIR_THRESH 0.02f

// Output layout (floats), concatenated in reference return order
#define O_Q     0
#define O_DIFF  8388608
#define O_CODE  8388609
#define O_EMB   8454145
#define O_CS    8585217
#define O_MEAN  8586241

// -------- device scratch --------
__device__ float g_embT[K_ * D_];          // embedding transposed [K][D]
__device__ float g_enorm[K_];              // ||e_k||^2
__device__ int   g_code[N_];
__device__ float g_embSumT[K_ * D_];       // per-code x-sum, [K][D]
__device__ float g_diff;
__device__ float g_n;
__device__ int   g_nrepair;
__device__ int   g_repair[N_];
__device__ int   g_hist[K_];
__device__ int   g_offset[K_];
__device__ int   g_cursor[K_];
__device__ int   g_rows[N_];
// swizzled bf16 hi/lo codebook images: 8 tiles of [128 codes][128 dims]
__device__ uint16_t g_EimgHi[K_ * D_];
__device__ uint16_t g_EimgLo[K_ * D_];

// ---------------- helpers ----------------
__device__ __forceinline__ uint32_t smem_u32(const void* p) {
    uint32_t a;
    asm("{ .reg .u64 t; cvta.to.shared.u64 t, %1; cvt.u32.u64 %0, t; }"
        : "=r"(a) : "l"(p));
    return a;
}
// float -> bf16 bits (round-to-nearest-even), finite inputs
__device__ __forceinline__ uint32_t f2bf(float x) {
    uint32_t u = __float_as_uint(x);
    return (u + 0x7fffu + ((u >> 16) & 1u)) >> 16;
}
__device__ __forceinline__ float bf2f(uint32_t h) {
    return __uint_as_float(h << 16);
}

__device__ __forceinline__ void ldmx4(uint32_t* r, uint32_t addr) {
    asm volatile("ldmatrix.sync.aligned.m8n8.x4.shared.b16 {%0,%1,%2,%3}, [%4];"
                 : "=r"(r[0]), "=r"(r[1]), "=r"(r[2]), "=r"(r[3]) : "r"(addr));
}
__device__ __forceinline__ void mma16816(float* c, const uint32_t* a,
                                         const uint32_t* b) {
    asm volatile(
        "mma.sync.aligned.m16n8k16.row.col.f32.bf16.bf16.f32 "
        "{%0,%1,%2,%3}, {%4,%5,%6,%7}, {%8,%9}, {%0,%1,%2,%3};"
        : "+f"(c[0]), "+f"(c[1]), "+f"(c[2]), "+f"(c[3])
        : "r"(a[0]), "r"(a[1]), "r"(a[2]), "r"(a[3]), "r"(b[0]), "r"(b[1]));
}
#define CP16(dst, src) \
    asm volatile("cp.async.ca.shared.global [%0], [%1], 16;" \
                 :: "r"(dst), "l"(src))
#define CP_COMMIT() asm volatile("cp.async.commit_group;" ::: "memory")
#define CP_WAIT0()  asm volatile("cp.async.wait_group 0;" ::: "memory")

// swizzled byte offset inside a [128][128] bf16 tile (256B rows, 16B chunks)
__device__ __forceinline__ uint32_t swoff(int r, int ch) {
    return (uint32_t)r * 256u + (uint32_t)((ch ^ (r & 7)) << 4);
}

// ============================================================
// 0) zero scratch
// ============================================================
__global__ void zero_kernel() {
    int t = threadIdx.x;
    if (t < K_) g_hist[t] = 0;
    if (t == 0) { g_diff = 0.0f; g_nrepair = 0; }
}

// ============================================================
// 1) enorm
// ============================================================
__global__ void enorm_kernel(const float* __restrict__ E) {
    int k = blockIdx.x * blockDim.x + threadIdx.x;
    if (k >= K_) return;
    float s = 0.0f;
#pragma unroll 8
    for (int d = 0; d < D_; d++) {
        float v = E[d * K_ + k];
        s = fmaf(v, v, s);
    }
    g_enorm[k] = s;
}

// ============================================================
// 2) transpose embedding [D,K] -> [K,D] (for gather/segsum)
// ============================================================
__global__ void transpose_kernel(const float* __restrict__ E) {
    __shared__ float tile[32][33];
    int k = blockIdx.x * 32 + threadIdx.x;
    int d = blockIdx.y * 32 + threadIdx.y;
    tile[threadIdx.y][threadIdx.x] = E[d * K_ + k];
    __syncthreads();
    int k2 = blockIdx.x * 32 + threadIdx.y;
    int d2 = blockIdx.y * 32 + threadIdx.x;
    g_embT[k2 * D_ + d2] = tile[threadIdx.x][threadIdx.y];
}

// ============================================================
// 2b) codebook -> bf16 hi/lo swizzled images
// ============================================================
__global__ void eimg_kernel(const float* __restrict__ E) {
    int idx = blockIdx.x * blockDim.x + threadIdx.x;   // 131072
    int k = idx & (K_ - 1);
    int d = idx >> 10;
    float v = E[d * K_ + k];
    uint32_t hi = f2bf(v);
    uint32_t lo = f2bf(v - bf2f(hi));
    int tile = k >> 7, r = k & 127;
    int pos = tile * 16384 + r * 128 + (((d >> 3) ^ (r & 7)) << 3) + (d & 7);
    g_EimgHi[pos] = (uint16_t)hi;
    g_EimgLo[pos] = (uint16_t)lo;
}

// ============================================================
// 3) argmin via mma.sync bf16 split GEMM
//    CTA: 128 rows x (8 tiles of 128 codes); 4 warps m64n64
//    warps (0,2) share rows 0-63, (1,3) rows 64-127; each pair
//    splits codes n in halves -> cross-warp combine via smem.
// ============================================================
#define SM_XH   0
#define SM_XL   32768
#define SM_E0   65536
#define SM_E1   131072
#define SM_ENS  196608
#define SM_CAND 200704
#define SM_ARG_TOTAL (200704 + 3072)

__device__ __forceinline__ void cp_tile(uint32_t dst, int tile, int tid) {
    const char* srcH = (const char*)g_EimgHi + (size_t)tile * 32768;
    const char* srcL = (const char*)g_EimgLo + (size_t)tile * 32768;
#pragma unroll
    for (int i = 0; i < 16; i++) {
        CP16(dst + tid * 16 + i * 2048, srcH + tid * 16 + i * 2048);
        CP16(dst + 32768 + tid * 16 + i * 2048, srcL + tid * 16 + i * 2048);
    }
}

__global__ __launch_bounds__(128, 1)
void argmin_mma_kernel(const float* __restrict__ in, float* __restrict__ out_code) {
    extern __shared__ char smem[];
    const uint32_t sb = smem_u32(smem);
    const int tid = threadIdx.x;
    const int lane = tid & 31;
    const int wid = tid >> 5;
    const int warp_m = wid & 1;      // 2 x m64
    const int warp_n = wid >> 1;     // 2 x n64
    const int row0 = blockIdx.x * 128;

    // prefetch E tile 0
    cp_tile(sb + SM_E0, 0, tid);
    CP_COMMIT();

    // ens -> smem
    float* ens = (float*)(smem + SM_ENS);
#pragma unroll
    for (int i = 0; i < 8; i++) ens[tid + i * 128] = g_enorm[tid + i * 128];

    // build X hi/lo swizzled images: thread owns dim-pair s, row half rh
    {
        const int s = tid & 63;
        const int rh = tid >> 6;
        const float2* gin = (const float2*)in;
#pragma unroll 4
        for (int rr = 0; rr < 64; rr++) {
            int r = rh * 64 + rr;
            float2 x = gin[(size_t)(row0 + r) * 64 + s];
            uint32_t h0 = f2bf(x.x), h1 = f2bf(x.y);
            uint32_t l0 = f2bf(x.x - bf2f(h0)), l1 = f2bf(x.y - bf2f(h1));
            uint32_t off = (uint32_t)r * 256u +
                           (uint32_t)((((s >> 2) ^ (r & 7)) << 4) + (s & 3) * 4);
            *(uint32_t*)(smem + SM_XH + off) = h0 | (h1 << 16);
            *(uint32_t*)(smem + SM_XL + off) = l0 | (l1 << 16);
        }
    }

    // per-thread ldmatrix lane mappings
    const int a_row = lane & 15;            // row within m16
    const int a_ksel = lane >> 4;           // 8-elem chunk select
    const int b_n = (lane & 7) + ((lane & 16) >> 1);  // row within n16
    const int b_ksel = (lane >> 3) & 1;

    float best[4][2], best2[4][2];
    int bidx[4][2];
#pragma unroll
    for (int mt = 0; mt < 4; mt++)
#pragma unroll
        for (int h = 0; h < 2; h++) {
            best[mt][h] = 3.4e38f; best2[mt][h] = 3.4e38f; bidx[mt][h] = 0;
        }

    for (int nt = 0; nt < 8; nt++) {
        CP_WAIT0();
        __syncthreads();
        if (nt < 7) { cp_tile(sb + (((nt + 1) & 1) ? SM_E1 : SM_E0), nt + 1, tid); CP_COMMIT(); }
        const uint32_t eb_hi = sb + ((nt & 1) ? SM_E1 : SM_E0);
        const uint32_t eb_lo = eb_hi + 32768;

        float acc[4][8][4];
#pragma unroll
        for (int mt = 0; mt < 4; mt++)
#pragma unroll
            for (int nn = 0; nn < 8; nn++)
#pragma unroll
                for (int i = 0; i < 4; i++) acc[mt][nn][i] = 0.0f;

#pragma unroll
        for (int kc = 0; kc < 8; kc++) {
            uint32_t Ah[4][4], Al[4][4];
#pragma unroll
            for (int mt = 0; mt < 4; mt++) {
                int r = warp_m * 64 + mt * 16 + a_row;
                uint32_t off = swoff(r, 2 * kc + a_ksel);
                ldmx4(Ah[mt], sb + SM_XH + off);
                ldmx4(Al[mt], sb + SM_XL + off);
            }
#pragma unroll
            for (int g = 0; g < 4; g++) {
                int n = warp_n * 64 + g * 16 + b_n;
                uint32_t off = swoff(n, 2 * kc + b_ksel);
                uint32_t Bh[4], Bl[4];
                ldmx4(Bh, eb_hi + off);
                ldmx4(Bl, eb_lo + off);
#pragma unroll
                for (int mt = 0; mt < 4; mt++) {
                    mma16816(acc[mt][2 * g],     Ah[mt], Bh);
                    mma16816(acc[mt][2 * g + 1], Ah[mt], Bh + 2);
                    mma16816(acc[mt][2 * g],     Ah[mt], Bl);
                    mma16816(acc[mt][2 * g + 1], Ah[mt], Bl + 2);
                    mma16816(acc[mt][2 * g],     Al[mt], Bh);
                    mma16816(acc[mt][2 * g + 1], Al[mt], Bh + 2);
                }
            }
        }

        // fold this tile's codes (this warp's n64 half) into running argmin
        const int cbase = nt * 128 + warp_n * 64 + (lane & 3) * 2;
#pragma unroll
        for (int mt = 0; mt < 4; mt++)
#pragma unroll
            for (int nn = 0; nn < 8; nn++)
#pragma unroll
                for (int i = 0; i < 4; i++) {
                    int c = cbase + nn * 8 + (i & 1);
                    int h = i >> 1;
                    float dist = fmaf(-2.0f, acc[mt][nn][i], ens[c]);
                    if (dist < best[mt][h]) {
                        best2[mt][h] = best[mt][h];
                        best[mt][h] = dist; bidx[mt][h] = c;
                    } else {
                        best2[mt][h] = fminf(best2[mt][h], dist);
                    }
                }
    }

    // quad reduction (lanes sharing a row differ in lane&3), stash to smem
    float* cb  = (float*)(smem + SM_CAND);          // [2][128]
    float* cb2 = (float*)(smem + SM_CAND + 1024);   // [2][128]
    int*   ci  = (int*)(smem + SM_CAND + 2048);     // [2][128]
#pragma unroll
    for (int mt = 0; mt < 4; mt++)
#pragma unroll
        for (int h = 0; h < 2; h++) {
            float b1 = best[mt][h], b2 = best2[mt][h];
            int i1 = bidx[mt][h];
#pragma unroll
            for (int off = 1; off <= 2; off <<= 1) {
                float ob1 = __shfl_xor_sync(0xffffffffu, b1, off);
                int   oi1 = __shfl_xor_sync(0xffffffffu, i1, off);
                float ob2 = __shfl_xor_sync(0xffffffffu, b2, off);
                if (ob1 < b1 || (ob1 == b1 && oi1 < i1)) {
                    b2 = fminf(b1, ob2);
                    b1 = ob1; i1 = oi1;
                } else {
                    b2 = fminf(b2, ob1);
                }
            }
            if ((lane & 3) == 0) {
                int lrow = warp_m * 64 + mt * 16 + (lane >> 2) + 8 * h;
                cb[warp_n * 128 + lrow] = b1;
                cb2[warp_n * 128 + lrow] = b2;
                ci[warp_n * 128 + lrow] = i1;
            }
        }
    __syncthreads();

    // combine the two code-half candidates for row `tid`
    {
        float b1a = cb[tid],       b2a = cb2[tid];       int i1a = ci[tid];
        float b1b = cb[128 + tid], b2b = cb2[128 + tid]; int i1b = ci[128 + tid];
        float fb, fs; int fi;
        if (b1b < b1a || (b1b == b1a && i1b < i1a)) {
            fb = b1b; fi = i1b; fs = fminf(b2b, b1a);
        } else {
            fb = b1a; fi = i1a; fs = fminf(b2a, b1b);
        }
        int row = row0 + tid;
        g_code[row] = fi;
        out_code[row] = (float)fi;
        if (fs - fb < REPAIR_THRESH) {
            int slot = atomicAdd(&g_nrepair, 1);
            if (slot < N_) g_repair[slot] = row;
        }
    }
}

// ============================================================
// 3b) repair: fp64 exact argmin for near-tie rows
// ============================================================
__global__ void repair_kernel(const float* __restrict__ in,
                              const float* __restrict__ E,
                              float* __restrict__ out_code) {
    __shared__ float xs[D_];
    __shared__ double sb_[256];
    __shared__ int si[256];
    int nrep = g_nrepair;
    if (nrep > N_) nrep = N_;
    for (int it = blockIdx.x; it < nrep; it += gridDim.x) {
        int row = g_repair[it];
        if (threadIdx.x < D_) xs[threadIdx.x] = in[row * D_ + threadIdx.x];
        __syncthreads();
        double b = 1e300; int bi = 0;
        for (int k = threadIdx.x; k < K_; k += 256) {
            double s = 0.0;
#pragma unroll 8
            for (int d = 0; d < D_; d++) {
                double df = (double)xs[d] - (double)E[d * K_ + k];
                s = fma(df, df, s);
            }
            if (s < b) { b = s; bi = k; }
        }
        sb_[threadIdx.x] = b; si[threadIdx.x] = bi;
        __syncthreads();
        for (int off = 128; off > 0; off >>= 1) {
            if (threadIdx.x < off) {
                double ob = sb_[threadIdx.x + off];
                int oi = si[threadIdx.x + off];
                if (ob < sb_[threadIdx.x] ||
                    (ob == sb_[threadIdx.x] && oi < si[threadIdx.x])) {
                    sb_[threadIdx.x] = ob; si[threadIdx.x] = oi;
                }
            }
            __syncthreads();
        }
        if (threadIdx.x == 0) {
            g_code[row] = si[0];
            out_code[row] = (float)si[0];
        }
        __syncthreads();
    }
}

// ============================================================
// 4) counting sort by code, then segmented sums
// ============================================================
__global__ void hist_kernel() {
    __shared__ int h[K_];
    for (int i = threadIdx.x; i < K_; i += 256) h[i] = 0;
    __syncthreads();
    int base = blockIdx.x * 2048;
    for (int i = threadIdx.x; i < 2048; i += 256)
        atomicAdd(&h[g_code[base + i]], 1);
    __syncthreads();
    for (int i = threadIdx.x; i < K_; i += 256)
        if (h[i]) atomicAdd(&g_hist[i], h[i]);
}

__global__ void scan_kernel() {
    __shared__ int s[K_];
    int t = threadIdx.x;
    int v0 = g_hist[t];
    s[t] = v0;
    __syncthreads();
    for (int off = 1; off < K_; off <<= 1) {
        int v = (t >= off) ? s[t - off] : 0;
        __syncthreads();
        s[t] += v;
        __syncthreads();
    }
    int excl = s[t] - v0;
    g_offset[t] = excl;
    g_cursor[t] = excl;
}

__global__ void scatter_kernel() {
    int row = blockIdx.x * 1024 + threadIdx.x;
    int c = g_code[row];
    int p = atomicAdd(&g_cursor[c], 1);
    g_rows[p] = row;
}

__global__ void segsum_kernel(const float* __restrict__ in) {
    __shared__ float red[128];
    const int k = blockIdx.x;
    const int t = threadIdx.x;
    const int start = g_offset[k];
    const int cnt = g_hist[k];
    const float ek = g_embT[k * D_ + t];
    float s = 0.0f, dsum = 0.0f;
    for (int i = 0; i < cnt; i++) {
        float x = in[(size_t)g_rows[start + i] * D_ + t];
        s += x;
        float df = x - ek;
        dsum = fmaf(df, df, dsum);
    }
    g_embSumT[k * D_ + t] = s;
    red[t] = dsum;
    __syncthreads();
    for (int off = 64; off > 0; off >>= 1) {
        if (t < off) red[t] += red[t + off];
        __syncthreads();
    }
    if (t == 0) atomicAdd(&g_diff, red[0]);
}

// ============================================================
// 5) quantize gather (one warp per row)
// ============================================================
__global__ void gather_q_kernel(float* __restrict__ out_q) {
    const int warp = threadIdx.x >> 5;
    const int lane = threadIdx.x & 31;
    const int row = blockIdx.x * 8 + warp;
    const int k = g_code[row];
    ((float4*)out_q)[row * 32 + lane] = ((const float4*)g_embT)[k * 32 + lane];
}

// ============================================================
// 6) finalize
// ============================================================
__global__ void finalizeA_kernel(const float* __restrict__ cs_in,
                                 float* __restrict__ out) {
    __shared__ float wsum[32];
    int k = threadIdx.x;
    float ncs = cs_in[k] * DECAY + (1.0f - DECAY) * (float)g_hist[k];
    out[O_CS + k] = ncs;
    float s = ncs;
#pragma unroll
    for (int off = 16; off > 0; off >>= 1)
        s += __shfl_down_sync(0xffffffffu, s, off);
    if ((k & 31) == 0) wsum[k >> 5] = s;
    __syncthreads();
    if (k < 32) {
        float v = wsum[k];
#pragma unroll
        for (int off = 16; off > 0; off >>= 1)
            v += __shfl_down_sync(0xffffffffu, v, off);
        if (k == 0) {
            g_n = v;
            out[O_DIFF] = VQ_COMMIT * g_diff / (float)(N_ * D_);
        }
    }
}

__global__ void finalizeB_kernel(const float* __restrict__ mean_in,
                                 float* __restrict__ out) {
    int idx = blockIdx.x * blockDim.x + threadIdx.x;
    if (idx >= D_ * K_) return;
    int d = idx >> 10;
    int k = idx & (K_ - 1);
    float em = mean_in[idx] * DECAY + (1.0f - DECAY) * g_embSumT[k * D_ + d];
    out[O_MEAN + idx] = em;
    float n = g_n;
    float ncs = out[O_CS + k];
    float cs = (ncs + EPSV) / (n + K_ * EPSV) * n;
    out[O_EMB + idx] = em / cs;
}

// ============================================================
extern "C" void kernel_launch(void* const* d_in, const int* in_sizes, int n_in,
                              void* d_out, int out_size) {
    const float* in      = (const float*)d_in[0];  // [B,T,D]
    const float* emb     = (const float*)d_in[1];  // [D,K]
    const float* cs_in   = (const float*)d_in[2];  // [K]
    const float* mean_in = (const float*)d_in[3];  // [D,K]
    float* out = (float*)d_out;

    static bool attr_set = false;
    if (!attr_set) {
        cudaFuncSetAttribute(argmin_mma_kernel,
                             cudaFuncAttributeMaxDynamicSharedMemorySize,
                             SM_ARG_TOTAL);
        attr_set = true;
    }

    zero_kernel<<<1, 1024>>>();
    eimg_kernel<<<(K_ * D_) / 256, 256>>>(emb);
    enorm_kernel<<<K_ / 256, 256>>>(emb);
    transpose_kernel<<<dim3(K_ / 32, D_ / 32), dim3(32, 32)>>>(emb);
    argmin_mma_kernel<<<N_ / 128, 128, SM_ARG_TOTAL>>>(in, out + O_CODE);
    repair_kernel<<<256, 256>>>(in, emb, out + O_CODE);
    hist_kernel<<<N_ / 2048, 256>>>();
    scan_kernel<<<1, 1024>>>();
    scatter_kernel<<<N_ / 1024, 1024>>>();
    segsum_kernel<<<K_, 128>>>(in);
    gather_q_kernel<<<N_ / 8, 256>>>(out + O_Q);
    finalizeA_kernel<<<1, 1024>>>(cs_in, out);
    finalizeB_kernel<<<(D_ * K_ + 255) / 256, 256>>>(mean_in, out);
}

// round 7
// speedup vs baseline: 3.0279x; 1.2199x over previous
#include <cuda_runtime.h>
#include <cuda_fp16.h>
#include <cstdint>

// Problem constants
#define D_   128
#define K_   1024
#define N_   65536            // B*T = 16*4096
#define DECAY 0.99f
#define EPSV  1e-5f
#define VQ_COMMIT 0.25f
#define REPAIR_THRESH  0.04f
#define REPAIR2_THRESH 2e-3f

// Output layout (floats), concatenated in reference return order
#define O_Q     0
#define O_DIFF  8388608
#define O_CODE  8388609
#define O_EMB   8454145
#define O_CS    8585217
#define O_MEAN  8586241

// -------- device scratch --------
__device__ float g_embT[K_ * D_];          // embedding transposed [K][D]
__device__ float g_enorm[K_];              // ||e_k||^2
__device__ int   g_code[N_];
__device__ float g_embSumT[K_ * D_];       // per-code x-sum, [K][D]
__device__ float g_diff;
__device__ float g_n;
__device__ int   g_nrepair;
__device__ int   g_repair[N_];
__device__ int   g_nrepair2;
__device__ int   g_repair2[4096];
__device__ int   g_hist[K_];
__device__ int   g_offset[K_];
__device__ int   g_cursor[K_];
__device__ int   g_rows[N_];
// swizzled fp16 codebook image: 8 tiles of [128 codes][128 dims]
__device__ uint16_t g_Eimg[K_ * D_];

// ---------------- helpers ----------------
__device__ __forceinline__ uint32_t smem_u32(const void* p) {
    uint32_t a;
    asm("{ .reg .u64 t; cvta.to.shared.u64 t, %1; cvt.u32.u64 %0, t; }"
        : "=r"(a) : "l"(p));
    return a;
}
__device__ __forceinline__ void ldmx4(uint32_t* r, uint32_t addr) {
    asm volatile("ldmatrix.sync.aligned.m8n8.x4.shared.b16 {%0,%1,%2,%3}, [%4];"
                 : "=r"(r[0]), "=r"(r[1]), "=r"(r[2]), "=r"(r[3]) : "r"(addr));
}
__device__ __forceinline__ void mma16816(float* c, const uint32_t* a,
                                         const uint32_t* b) {
    asm volatile(
        "mma.sync.aligned.m16n8k16.row.col.f32.f16.f16.f32 "
        "{%0,%1,%2,%3}, {%4,%5,%6,%7}, {%8,%9}, {%0,%1,%2,%3};"
        : "+f"(c[0]), "+f"(c[1]), "+f"(c[2]), "+f"(c[3])
        : "r"(a[0]), "r"(a[1]), "r"(a[2]), "r"(a[3]), "r"(b[0]), "r"(b[1]));
}
#define CP16(dst, src) \
    asm volatile("cp.async.ca.shared.global [%0], [%1], 16;" \
                 :: "r"(dst), "l"(src))
#define CP_COMMIT() asm volatile("cp.async.commit_group;" ::: "memory")
#define CP_WAIT0()  asm volatile("cp.async.wait_group 0;" ::: "memory")

// swizzled byte offset inside a [128][128] fp16 tile (256B rows, 16B chunks)
__device__ __forceinline__ uint32_t swoff(int r, int ch) {
    return (uint32_t)r * 256u + (uint32_t)((ch ^ (r & 7)) << 4);
}

// ============================================================
// 1) eimg: codebook -> fp16 swizzled image  (+ zero scratch)
// ============================================================
__global__ void eimg_kernel(const float* __restrict__ E) {
    int idx = blockIdx.x * blockDim.x + threadIdx.x;   // 131072
    if (idx < K_) g_hist[idx] = 0;
    if (idx == 0) { g_diff = 0.0f; g_nrepair = 0; g_nrepair2 = 0; }
    int k = idx & (K_ - 1);
    int d = idx >> 10;
    float v = E[d * K_ + k];
    __half h = __float2half_rn(v);
    int tile = k >> 7, r = k & 127;
    int pos = tile * 16384 + r * 128 + (((d >> 3) ^ (r & 7)) << 3) + (d & 7);
    g_Eimg[pos] = __half_as_ushort(h);
}

// ============================================================
// 2) enorm (fp32 exact)
// ============================================================
__global__ void enorm_kernel(const float* __restrict__ E) {
    int k = blockIdx.x * blockDim.x + threadIdx.x;
    if (k >= K_) return;
    float s = 0.0f;
#pragma unroll 8
    for (int d = 0; d < D_; d++) {
        float v = E[d * K_ + k];
        s = fmaf(v, v, s);
    }
    g_enorm[k] = s;
}

// ============================================================
// 3) transpose embedding [D,K] -> [K,D]
// ============================================================
__global__ void transpose_kernel(const float* __restrict__ E) {
    __shared__ float tile[32][33];
    int k = blockIdx.x * 32 + threadIdx.x;
    int d = blockIdx.y * 32 + threadIdx.y;
    tile[threadIdx.y][threadIdx.x] = E[d * K_ + k];
    __syncthreads();
    int k2 = blockIdx.x * 32 + threadIdx.y;
    int d2 = blockIdx.y * 32 + threadIdx.x;
    g_embT[k2 * D_ + d2] = tile[threadIdx.x][threadIdx.y];
}

// ============================================================
// 4) argmin via mma.sync fp16 2-term split GEMM
//    CTA: 128 rows x 1024 codes, 256 threads, 8 warps m64n32
// ============================================================
#define SM_XH   0
#define SM_XL   32768
#define SM_E0   65536
#define SM_E1   98304
#define SM_ENS  131072
#define SM_CAND 135168
#define SM_ARG_TOTAL (135168 + 6144)

__device__ __forceinline__ void cp_tile(uint32_t dst, int tile, int tid) {
    const char* src = (const char*)g_Eimg + (size_t)tile * 32768;
#pragma unroll
    for (int i = 0; i < 8; i++)
        CP16(dst + tid * 16 + i * 4096, src + tid * 16 + i * 4096);
}

__global__ __launch_bounds__(256, 1)
void argmin_mma_kernel(const float* __restrict__ in, float* __restrict__ out_code) {
    extern __shared__ char smem[];
    const uint32_t sb = smem_u32(smem);
    const int tid = threadIdx.x;
    const int lane = tid & 31;
    const int wid = tid >> 5;
    const int warp_m = wid & 1;      // 2 x m64
    const int warp_q = wid >> 1;     // 4 x n32
    const int row0 = blockIdx.x * 128;

    // prefetch E tile 0
    cp_tile(sb + SM_E0, 0, tid);
    CP_COMMIT();

    // ens -> smem
    float* ens = (float*)(smem + SM_ENS);
#pragma unroll
    for (int i = 0; i < 4; i++) ens[tid + i * 256] = g_enorm[tid + i * 256];

    // build X hi/lo fp16 swizzled images
    {
        const int s = tid & 63;          // dim-pair
        const int rh = tid >> 6;         // row quarter
        const float2* gin = (const float2*)in;
#pragma unroll 4
        for (int rr = 0; rr < 32; rr++) {
            int r = rh * 32 + rr;
            float2 x = gin[(size_t)(row0 + r) * 64 + s];
            __half h0 = __float2half_rn(x.x);
            __half h1 = __float2half_rn(x.y);
            __half l0 = __float2half_rn(x.x - __half2float(h0));
            __half l1 = __float2half_rn(x.y - __half2float(h1));
            uint32_t off = (uint32_t)r * 256u +
                           (uint32_t)((((s >> 2) ^ (r & 7)) << 4) + (s & 3) * 4);
            *(uint32_t*)(smem + SM_XH + off) =
                (uint32_t)__half_as_ushort(h0) | ((uint32_t)__half_as_ushort(h1) << 16);
            *(uint32_t*)(smem + SM_XL + off) =
                (uint32_t)__half_as_ushort(l0) | ((uint32_t)__half_as_ushort(l1) << 16);
        }
    }

    // ldmatrix lane mappings
    const int a_row = lane & 15;
    const int a_ksel = lane >> 4;
    const int b_n = (lane & 7) + ((lane & 16) >> 1);
    const int b_ksel = (lane >> 3) & 1;

    float best[4][2], best2[4][2];
    int bidx[4][2];
#pragma unroll
    for (int mt = 0; mt < 4; mt++)
#pragma unroll
        for (int h = 0; h < 2; h++) {
            best[mt][h] = 3.4e38f; best2[mt][h] = 3.4e38f; bidx[mt][h] = 0;
        }

    for (int nt = 0; nt < 8; nt++) {
        CP_WAIT0();
        __syncthreads();
        if (nt < 7) { cp_tile(sb + (((nt + 1) & 1) ? SM_E1 : SM_E0), nt + 1, tid); CP_COMMIT(); }
        const uint32_t eb = sb + ((nt & 1) ? SM_E1 : SM_E0);

        float acc[4][4][4];
#pragma unroll
        for (int mt = 0; mt < 4; mt++)
#pragma unroll
            for (int nn = 0; nn < 4; nn++)
#pragma unroll
                for (int i = 0; i < 4; i++) acc[mt][nn][i] = 0.0f;

#pragma unroll
        for (int kc = 0; kc < 8; kc++) {
            uint32_t Ah[4][4], Al[4][4];
#pragma unroll
            for (int mt = 0; mt < 4; mt++) {
                int r = warp_m * 64 + mt * 16 + a_row;
                uint32_t off = swoff(r, 2 * kc + a_ksel);
                ldmx4(Ah[mt], sb + SM_XH + off);
                ldmx4(Al[mt], sb + SM_XL + off);
            }
#pragma unroll
            for (int g = 0; g < 2; g++) {
                int n = warp_q * 32 + g * 16 + b_n;
                uint32_t off = swoff(n, 2 * kc + b_ksel);
                uint32_t Bh[4];
                ldmx4(Bh, eb + off);
#pragma unroll
                for (int mt = 0; mt < 4; mt++) {
                    mma16816(acc[mt][2 * g],     Ah[mt], Bh);
                    mma16816(acc[mt][2 * g + 1], Ah[mt], Bh + 2);
                    mma16816(acc[mt][2 * g],     Al[mt], Bh);
                    mma16816(acc[mt][2 * g + 1], Al[mt], Bh + 2);
                }
            }
        }

        // fold this tile's codes (this warp's n32) into running argmin
        const int cbase = nt * 128 + warp_q * 32 + (lane & 3) * 2;
#pragma unroll
        for (int mt = 0; mt < 4; mt++)
#pragma unroll
            for (int nn = 0; nn < 4; nn++)
#pragma unroll
                for (int i = 0; i < 4; i++) {
                    int c = cbase + nn * 8 + (i & 1);
                    int h = i >> 1;
                    float dist = fmaf(-2.0f, acc[mt][nn][i], ens[c]);
                    if (dist < best[mt][h]) {
                        best2[mt][h] = best[mt][h];
                        best[mt][h] = dist; bidx[mt][h] = c;
                    } else {
                        best2[mt][h] = fminf(best2[mt][h], dist);
                    }
                }
    }

    // quad reduction (lanes sharing a row differ in lane&3), stash to smem
    float* cb  = (float*)(smem + SM_CAND);          // [4][128]
    float* cb2 = (float*)(smem + SM_CAND + 2048);   // [4][128]
    int*   ci  = (int*)(smem + SM_CAND + 4096);     // [4][128]
#pragma unroll
    for (int mt = 0; mt < 4; mt++)
#pragma unroll
        for (int h = 0; h < 2; h++) {
            float b1 = best[mt][h], b2 = best2[mt][h];
            int i1 = bidx[mt][h];
#pragma unroll
            for (int off = 1; off <= 2; off <<= 1) {
                float ob1 = __shfl_xor_sync(0xffffffffu, b1, off);
                int   oi1 = __shfl_xor_sync(0xffffffffu, i1, off);
                float ob2 = __shfl_xor_sync(0xffffffffu, b2, off);
                if (ob1 < b1 || (ob1 == b1 && oi1 < i1)) {
                    b2 = fminf(b1, ob2);
                    b1 = ob1; i1 = oi1;
                } else {
                    b2 = fminf(b2, ob1);
                }
            }
            if ((lane & 3) == 0) {
                int lrow = warp_m * 64 + mt * 16 + (lane >> 2) + 8 * h;
                cb[warp_q * 128 + lrow] = b1;
                cb2[warp_q * 128 + lrow] = b2;
                ci[warp_q * 128 + lrow] = i1;
            }
        }
    __syncthreads();

    // combine the four code-quarter candidates for row `tid`
    if (tid < 128) {
        float fb = cb[tid], fs = cb2[tid];
        int fi = ci[tid];
#pragma unroll
        for (int q = 1; q < 4; q++) {
            float b = cb[q * 128 + tid], b2 = cb2[q * 128 + tid];
            int i = ci[q * 128 + tid];
            if (b < fb || (b == fb && i < fi)) {
                fs = fminf(b2, fb); fb = b; fi = i;
            } else {
                fs = fminf(fs, b);
            }
        }
        int row = row0 + tid;
        g_code[row] = fi;
        out_code[row] = (float)fi;
        if (fs - fb < REPAIR_THRESH) {
            int slot = atomicAdd(&g_nrepair, 1);
            if (slot < N_) g_repair[slot] = row;
        }
    }
}

// ============================================================
// 5) repair stage 1: fp32 re-rank, 4 rows per block
// ============================================================
__global__ void repair1_kernel(const float* __restrict__ in,
                               const float* __restrict__ E,
                               float* __restrict__ out_code) {
    __shared__ float xs[4][128];
    __shared__ int rows_s[4];
    __shared__ float sb1[256], sb2[256];
    __shared__ int si[256];
    const int tid = threadIdx.x;
    int nrep = g_nrepair;
    if (nrep > N_) nrep = N_;
    for (int base = blockIdx.x * 4; base < nrep; base += gridDim.x * 4) {
        int nr = nrep - base; if (nr > 4) nr = 4;
        if (tid < nr) rows_s[tid] = g_repair[base + tid];
        __syncthreads();
        for (int j = tid; j < nr * 128; j += 256)
            xs[j >> 7][j & 127] = in[(size_t)rows_s[j >> 7] * D_ + (j & 127)];
        __syncthreads();

        float best[4], best2[4]; int bidx[4];
#pragma unroll
        for (int r = 0; r < 4; r++) { best[r] = 3.4e38f; best2[r] = 3.4e38f; bidx[r] = 0; }

#pragma unroll
        for (int kk = 0; kk < 4; kk++) {
            int k = tid + kk * 256;
            float s0[4] = {0, 0, 0, 0}, s1[4] = {0, 0, 0, 0};
#pragma unroll 4
            for (int d = 0; d < D_; d += 2) {
                float e0 = E[d * K_ + k];
                float e1 = E[(d + 1) * K_ + k];
#pragma unroll
                for (int r = 0; r < 4; r++) {
                    float d0 = xs[r][d] - e0;
                    float d1 = xs[r][d + 1] - e1;
                    s0[r] = fmaf(d0, d0, s0[r]);
                    s1[r] = fmaf(d1, d1, s1[r]);
                }
            }
#pragma unroll
            for (int r = 0; r < 4; r++) {
                float ds = s0[r] + s1[r];
                if (ds < best[r]) { best2[r] = best[r]; best[r] = ds; bidx[r] = k; }
                else best2[r] = fminf(best2[r], ds);
            }
        }

        for (int r = 0; r < 4; r++) {
            sb1[tid] = best[r]; sb2[tid] = best2[r]; si[tid] = bidx[r];
            __syncthreads();
            for (int off = 128; off > 0; off >>= 1) {
                if (tid < off) {
                    float ob = sb1[tid + off], ob2 = sb2[tid + off];
                    int oi = si[tid + off];
                    if (ob < sb1[tid] || (ob == sb1[tid] && oi < si[tid])) {
                        sb2[tid] = fminf(sb1[tid], ob2);
                        sb1[tid] = ob; si[tid] = oi;
                    } else {
                        sb2[tid] = fminf(sb2[tid], ob);
                    }
                }
                __syncthreads();
            }
            if (tid == 0 && r < nr) {
                int row = rows_s[r];
                g_code[row] = si[0];
                out_code[row] = (float)si[0];
                if (sb2[0] - sb1[0] < REPAIR2_THRESH) {
                    int slot = atomicAdd(&g_nrepair2, 1);
                    if (slot < 4096) g_repair2[slot] = row;
                }
            }
            __syncthreads();
        }
    }
}

// ============================================================
// 6) repair stage 2: fp64 exact for ultra-ties
// ============================================================
__global__ void repair2_kernel(const float* __restrict__ in,
                               const float* __restrict__ E,
                               float* __restrict__ out_code) {
    __shared__ float xs[D_];
    __shared__ double sbd[256];
    __shared__ int si[256];
    int nrep = g_nrepair2;
    if (nrep > 4096) nrep = 4096;
    for (int it = blockIdx.x; it < nrep; it += gridDim.x) {
        int row = g_repair2[it];
        if (threadIdx.x < D_) xs[threadIdx.x] = in[(size_t)row * D_ + threadIdx.x];
        __syncthreads();
        double b = 1e300; int bi = 0;
        for (int k = threadIdx.x; k < K_; k += 256) {
            double s = 0.0;
#pragma unroll 8
            for (int d = 0; d < D_; d++) {
                double df = (double)xs[d] - (double)E[d * K_ + k];
                s = fma(df, df, s);
            }
            if (s < b) { b = s; bi = k; }
        }
        sbd[threadIdx.x] = b; si[threadIdx.x] = bi;
        __syncthreads();
        for (int off = 128; off > 0; off >>= 1) {
            if (threadIdx.x < off) {
                double ob = sbd[threadIdx.x + off];
                int oi = si[threadIdx.x + off];
                if (ob < sbd[threadIdx.x] ||
                    (ob == sbd[threadIdx.x] && oi < si[threadIdx.x])) {
                    sbd[threadIdx.x] = ob; si[threadIdx.x] = oi;
                }
            }
            __syncthreads();
        }
        if (threadIdx.x == 0) {
            g_code[row] = si[0];
            out_code[row] = (float)si[0];
        }
        __syncthreads();
    }
}

// ============================================================
// 7) counting sort by code, then segmented sums (+ quantize out)
// ============================================================
__global__ void hist_kernel() {
    __shared__ int h[K_];
    for (int i = threadIdx.x; i < K_; i += 256) h[i] = 0;
    __syncthreads();
    int base = blockIdx.x * 2048;
    for (int i = threadIdx.x; i < 2048; i += 256)
        atomicAdd(&h[g_code[base + i]], 1);
    __syncthreads();
    for (int i = threadIdx.x; i < K_; i += 256)
        if (h[i]) atomicAdd(&g_hist[i], h[i]);
}

__global__ void scan_kernel() {
    __shared__ int s[K_];
    int t = threadIdx.x;
    int v0 = g_hist[t];
    s[t] = v0;
    __syncthreads();
    for (int off = 1; off < K_; off <<= 1) {
        int v = (t >= off) ? s[t - off] : 0;
        __syncthreads();
        s[t] += v;
        __syncthreads();
    }
    int excl = s[t] - v0;
    g_offset[t] = excl;
    g_cursor[t] = excl;
}

__global__ void scatter_kernel() {
    int row = blockIdx.x * 1024 + threadIdx.x;
    int c = g_code[row];
    int p = atomicAdd(&g_cursor[c], 1);
    g_rows[p] = row;
}

__global__ void segsum_kernel(const float* __restrict__ in,
                              float* __restrict__ out_q) {
    __shared__ float red[128];
    const int k = blockIdx.x;
    const int t = threadIdx.x;
    const int start = g_offset[k];
    const int cnt = g_hist[k];
    const float ek = g_embT[k * D_ + t];
    float s = 0.0f, dsum = 0.0f;
    for (int i = 0; i < cnt; i++) {
        int row = g_rows[start + i];
        float x = in[(size_t)row * D_ + t];
        s += x;
        float df = x - ek;
        dsum = fmaf(df, df, dsum);
        out_q[(size_t)row * D_ + t] = ek;
    }
    g_embSumT[k * D_ + t] = s;
    red[t] = dsum;
    __syncthreads();
    for (int off = 64; off > 0; off >>= 1) {
        if (t < off) red[t] += red[t + off];
        __syncthreads();
    }
    if (t == 0) atomicAdd(&g_diff, red[0]);
}

// ============================================================
// 8) finalize
// ============================================================
__global__ void finalizeA_kernel(const float* __restrict__ cs_in,
                                 float* __restrict__ out) {
    __shared__ float wsum[32];
    int k = threadIdx.x;
    float ncs = cs_in[k] * DECAY + (1.0f - DECAY) * (float)g_hist[k];
    out[O_CS + k] = ncs;
    float s = ncs;
#pragma unroll
    for (int off = 16; off > 0; off >>= 1)
        s += __shfl_down_sync(0xffffffffu, s, off);
    if ((k & 31) == 0) wsum[k >> 5] = s;
    __syncthreads();
    if (k < 32) {
        float v = wsum[k];
#pragma unroll
        for (int off = 16; off > 0; off >>= 1)
            v += __shfl_down_sync(0xffffffffu, v, off);
        if (k == 0) {
            g_n = v;
            out[O_DIFF] = VQ_COMMIT * g_diff / (float)(N_ * D_);
        }
    }
}

__global__ void finalizeB_kernel(const float* __restrict__ mean_in,
                                 float* __restrict__ out) {
    int idx = blockIdx.x * blockDim.x + threadIdx.x;
    if (idx >= D_ * K_) return;
    int d = idx >> 10;
    int k = idx & (K_ - 1);
    float em = mean_in[idx] * DECAY + (1.0f - DECAY) * g_embSumT[k * D_ + d];
    out[O_MEAN + idx] = em;
    float n = g_n;
    float ncs = out[O_CS + k];
    float cs = (ncs + EPSV) / (n + K_ * EPSV) * n;
    out[O_EMB + idx] = em / cs;
}

// ============================================================
extern "C" void kernel_launch(void* const* d_in, const int* in_sizes, int n_in,
                              void* d_out, int out_size) {
    const float* in      = (const float*)d_in[0];  // [B,T,D]
    const float* emb     = (const float*)d_in[1];  // [D,K]
    const float* cs_in   = (const float*)d_in[2];  // [K]
    const float* mean_in = (const float*)d_in[3];  // [D,K]
    float* out = (float*)d_out;

    static bool attr_set = false;
    if (!attr_set) {
        cudaFuncSetAttribute(argmin_mma_kernel,
                             cudaFuncAttributeMaxDynamicSharedMemorySize,
                             SM_ARG_TOTAL);
        attr_set = true;
    }

    eimg_kernel<<<(K_ * D_) / 256, 256>>>(emb);                       // 1
    enorm_kernel<<<K_ / 256, 256>>>(emb);                             // 2
    transpose_kernel<<<dim3(K_ / 32, D_ / 32), dim3(32, 32)>>>(emb);  // 3
    argmin_mma_kernel<<<N_ / 128, 256, SM_ARG_TOTAL>>>(in, out + O_CODE); // 4 (ncu slot)
    repair1_kernel<<<256, 256>>>(in, emb, out + O_CODE);              // 5
    repair2_kernel<<<64, 256>>>(in, emb, out + O_CODE);               // 6
    hist_kernel<<<N_ / 2048, 256>>>();                                // 7
    scan_kernel<<<1, 1024>>>();                                       // 8
    scatter_kernel<<<N_ / 1024, 1024>>>();                            // 9
    segsum_kernel<<<K_, 128>>>(in, out + O_Q);                        // 10
    finalizeA_kernel<<<1, 1024>>>(cs_in, out);                        // 11
    finalizeB_kernel<<<(D_ * K_ + 255) / 256, 256>>>(mean_in, out);   // 12
}